// round 9
// baseline (speedup 1.0000x reference)
#include <cuda_runtime.h>
#include <cuda_bf16.h>
#include <math.h>

#define N_   8192
#define D_   2048
#define P_   512
#define NB_  16          // k0 partition blocks (512 samples each)
#define EPSF 1e-12f
#define S_   8           // k1 bulk-copy ring depth (8 x 8KB = 64KB dynamic smem)

// ---------------- scratch (device globals; no allocation allowed) ----------
__device__ int   g_count[P_];
__device__ int   g_offset[P_];
__device__ int   g_members[N_];
__device__ int   g_pc[NB_][P_];       // per-partition class histograms
__device__ __nv_bfloat16 g_cbf[3][P_][D_];   // unit centers, bf16
__device__ float g_expsum[3][P_];     // per-row sum of exp(2*dot)
__device__ float g_sumnorm;           // sum ||s_c|| over all (m, c)
__device__ float g_sumdiag;           // sum of diagonal dots over all (p, i)

// ---------------- helpers --------------------------------------------------
__device__ __forceinline__ float warpSum(float v) {
#pragma unroll
    for (int o = 16; o; o >>= 1) v += __shfl_xor_sync(0xffffffffu, v, o);
    return v;
}
__device__ __forceinline__ unsigned bfpack(float lo, float hi) {
    unsigned a = (unsigned)__bfloat16_as_ushort(__float2bfloat16_rn(lo));
    unsigned b = (unsigned)__bfloat16_as_ushort(__float2bfloat16_rn(hi));
    return a | (b << 16);
}
__device__ __forceinline__ void mbar_init(unsigned mbar, unsigned count) {
    asm volatile("mbarrier.init.shared.b64 [%0], %1;" :: "r"(mbar), "r"(count) : "memory");
}
__device__ __forceinline__ void mbar_expect_tx(unsigned mbar, unsigned tx) {
    asm volatile("mbarrier.arrive.expect_tx.shared.b64 _, [%0], %1;" :: "r"(mbar), "r"(tx) : "memory");
}
__device__ __forceinline__ void mbar_wait(unsigned mbar, unsigned parity) {
    asm volatile(
        "{\n\t"
        ".reg .pred P1;\n\t"
        "WAIT_LOOP_%=:\n\t"
        "mbarrier.try_wait.parity.acquire.cta.shared::cta.b64 P1, [%0], %1, 0x989680;\n\t"
        "@P1 bra.uni WAIT_DONE_%=;\n\t"
        "bra.uni WAIT_LOOP_%=;\n\t"
        "WAIT_DONE_%=:\n\t"
        "}"
        :: "r"(mbar), "r"(parity) : "memory");
}
__device__ __forceinline__ void bulk_cp(void* dst, const void* src, unsigned bytes, unsigned mbar) {
    unsigned d = (unsigned)__cvta_generic_to_shared(dst);
    asm volatile(
        "cp.async.bulk.shared::cta.global.mbarrier::complete_tx::bytes [%0], [%1], %2, [%3];"
        :: "r"(d), "l"(src), "r"(bytes), "r"(mbar) : "memory");
}

// ---------------- kernel 0a: per-partition histogram + zero accumulators ---
__global__ void __launch_bounds__(512) k0a_hist(const int* __restrict__ label) {
    __shared__ int h[P_];
    int t = threadIdx.x, b = blockIdx.x;
    h[t] = 0;
    __syncthreads();
    int l = __ldg(&label[b * 512 + t]);
    atomicAdd(&h[l], 1);
    __syncthreads();
    g_pc[b][t] = h[t];
    if (b == 0) {
        g_expsum[0][t] = 0.f; g_expsum[1][t] = 0.f; g_expsum[2][t] = 0.f;
        if (t == 0) { g_sumnorm = 0.f; g_sumdiag = 0.f; }
    }
}

// ---------------- kernel 0b: redundant scan + parallel fill (grid NB_) -----
__global__ void __launch_bounds__(512) k0b_fill(const int* __restrict__ label) {
    __shared__ int cur[P_];
    __shared__ int ws[16];
    int t = threadIdx.x, b = blockIdx.x, lane = t & 31, w = t >> 5;

    int pref = 0, tot = 0;
#pragma unroll
    for (int bb = 0; bb < NB_; bb++) {
        int v = g_pc[bb][t];
        if (bb < b) pref += v;
        tot += v;
    }
    // exclusive scan of tot over the 512 classes (shfl + warp sums)
    int inc = tot;
#pragma unroll
    for (int o = 1; o < 32; o <<= 1) {
        int v = __shfl_up_sync(0xffffffffu, inc, o);
        if (lane >= o) inc += v;
    }
    if (lane == 31) ws[w] = inc;
    __syncthreads();
    if (t < 32) {
        int v = (t < 16) ? ws[t] : 0;
        int s = v;
#pragma unroll
        for (int o = 1; o < 32; o <<= 1) {
            int u = __shfl_up_sync(0xffffffffu, s, o);
            if (lane >= o) s += u;
        }
        if (t < 16) ws[t] = s - v;
    }
    __syncthreads();
    int exc = ws[w] + inc - tot;          // exclusive class prefix
    if (b == 0) { g_count[t] = tot; g_offset[t] = exc; }
    cur[t] = exc + pref;                  // this partition's write base
    __syncthreads();
    int i = b * 512 + t;
    int c = __ldg(&label[i]);
    int pos = atomicAdd(&cur[c], 1);
    g_members[pos] = i;
}

// ---------------- kernel 1: centers via cp.async.bulk ring ------------------
// grid (P_, 3), block 256. 8-stage ring of full 8KB rows in DYNAMIC smem.
// One bulk-copy instruction per row (thread 0) -> near-zero LSU issue cost;
// 3 blocks/SM x 64KB = ~192KB in flight -> DRAM-throughput-bound.
__global__ void __launch_bounds__(256) k1_centers(const float* __restrict__ f0,
                                                  const float* __restrict__ f1,
                                                  const float* __restrict__ f2) {
    extern __shared__ __align__(16) float stg[];   // [S_][D_]
    __shared__ __align__(8) unsigned long long mbar[S_];
    __shared__ float wred[2][8];
    __shared__ int rows_s[32];

    int c = blockIdx.x, m = blockIdx.y;
    const float* f = (m == 0) ? f0 : ((m == 1) ? f1 : f2);
    int off = g_offset[c];
    int K   = g_count[c];
    int t   = threadIdx.x, w = t >> 5, lane = t & 31;

    if (t < 32 && t < K) rows_s[t] = __ldg(&g_members[off + t]);
    if (t == 0) {
#pragma unroll
        for (int s = 0; s < S_; s++)
            mbar_init((unsigned)__cvta_generic_to_shared(&mbar[s]), 1);
        asm volatile("fence.proxy.async;" ::: "memory");
    }
    __syncthreads();

    if (t == 0) {
#pragma unroll
        for (int s = 0; s < S_; s++) {
            if (s < K) {
                unsigned mb = (unsigned)__cvta_generic_to_shared(&mbar[s]);
                mbar_expect_tx(mb, D_ * 4);
                bulk_cp(&stg[s * D_], f + (size_t)rows_s[s] * D_, D_ * 4, mb);
            }
        }
    }

    float a0 = 0.f, a1 = 0.f, a2 = 0.f, a3 = 0.f;
    float a4 = 0.f, a5 = 0.f, a6 = 0.f, a7 = 0.f;

    for (int k = 0; k < K; k++) {
        int sb = k & (S_ - 1);
        unsigned mb = (unsigned)__cvta_generic_to_shared(&mbar[sb]);
        mbar_wait(mb, (unsigned)((k >> 3) & 1));
        float4 x = *(const float4*)&stg[sb * D_ + t * 4];
        float4 y = *(const float4*)&stg[sb * D_ + 1024 + t * 4];
        float ss = warpSum(x.x * x.x + x.y * x.y + x.z * x.z + x.w * x.w
                         + y.x * y.x + y.y * y.y + y.z * y.z + y.w * y.w);
        if (lane == 0) wred[k & 1][w] = ss;
        __syncthreads();               // reduction ready AND stage consumed
        if (t == 0 && k + S_ < K) {    // re-arm the just-freed stage
            int idx = k + S_;
            int row = (idx < 32) ? rows_s[idx] : __ldg(&g_members[off + idx]);
            mbar_expect_tx(mb, D_ * 4);
            bulk_cp(&stg[sb * D_], f + (size_t)row * D_, D_ * 4, mb);
        }
        float tot = wred[k & 1][0] + wred[k & 1][1] + wred[k & 1][2] + wred[k & 1][3]
                  + wred[k & 1][4] + wred[k & 1][5] + wred[k & 1][6] + wred[k & 1][7];
        float inv = rsqrtf(fmaxf(tot, 1e-24f));
        a0 += x.x * inv; a1 += x.y * inv; a2 += x.z * inv; a3 += x.w * inv;
        a4 += y.x * inv; a5 += y.y * inv; a6 += y.z * inv; a7 += y.w * inv;
    }

    float ss2 = a0 * a0 + a1 * a1 + a2 * a2 + a3 * a3
              + a4 * a4 + a5 * a5 + a6 * a6 + a7 * a7;
    ss2 = warpSum(ss2);
    __syncthreads();
    if (lane == 0) wred[0][w] = ss2;
    __syncthreads();
    float tot2 = wred[0][0] + wred[0][1] + wred[0][2] + wred[0][3]
               + wred[0][4] + wred[0][5] + wred[0][6] + wred[0][7];
    float nrm  = sqrtf(tot2);
    float inv2 = 1.f / fmaxf(nrm, EPSF);

    __nv_bfloat16* cb = &g_cbf[m][c][0];
    uint2 u0, u1;
    u0.x = bfpack(a0 * inv2, a1 * inv2); u0.y = bfpack(a2 * inv2, a3 * inv2);
    u1.x = bfpack(a4 * inv2, a5 * inv2); u1.y = bfpack(a6 * inv2, a7 * inv2);
    *(uint2*)(cb + 4 * t)         = u0;
    *(uint2*)(cb + 4 * (t + 256)) = u1;
    if (t == 0) atomicAdd(&g_sumnorm, nrm);
}

// ---------------- kernel 2: bf16 mma GEMMs + fused exp-sum epilogue --------
// 32(M)x64(N) tiles, grid (8, 16, 3) = 384 blocks (2.6 waves), block 128.
// 4 warps as 2(M)x2(N); warp tile 16x32. Operands are L2-resident (12MB).
#define KC_ 64
__device__ __forceinline__ unsigned sw_off(int row, int g) {
    return (unsigned)(row * 128 + ((g ^ (row & 7)) << 4));
}

__global__ void __launch_bounds__(128) k2_gemm() {
    int p  = blockIdx.z;
    int pa = (p == 2) ? 1 : 0;
    int pb = (p == 0) ? 1 : 2;
    const __nv_bfloat16* A = &g_cbf[pa][0][0];
    const __nv_bfloat16* B = &g_cbf[pb][0][0];

    __shared__ __align__(16) unsigned char As[32 * 128];
    __shared__ __align__(16) unsigned char Bs[64 * 128];
    unsigned asb = (unsigned)__cvta_generic_to_shared(As);
    unsigned bsb = (unsigned)__cvta_generic_to_shared(Bs);

    int t = threadIdx.x, lane = t & 31, warp = t >> 5;
    int wr = warp >> 1, wc = warp & 1;
    int brow = blockIdx.y * 32, bcol = blockIdx.x * 64;

    float acc[4][4];
#pragma unroll
    for (int nt = 0; nt < 4; nt++)
#pragma unroll
        for (int e = 0; e < 4; e++) acc[nt][e] = 0.f;

    int rsel = lane & 15, gsel = lane >> 4;

    uint4 ga[2], gb[4];
#pragma unroll
    for (int j = 0; j < 2; j++) {
        int i = t + j * 128, row = i >> 3, g = i & 7;
        ga[j] = *(const uint4*)(A + (size_t)(brow + row) * D_ + g * 8);
    }
#pragma unroll
    for (int j = 0; j < 4; j++) {
        int i = t + j * 128, row = i >> 3, g = i & 7;
        gb[j] = *(const uint4*)(B + (size_t)(bcol + row) * D_ + g * 8);
    }

    for (int kc = 0; kc < D_ / KC_; kc++) {
#pragma unroll
        for (int j = 0; j < 2; j++) {
            int i = t + j * 128, row = i >> 3, g = i & 7;
            *(uint4*)(As + sw_off(row, g)) = ga[j];
        }
#pragma unroll
        for (int j = 0; j < 4; j++) {
            int i = t + j * 128, row = i >> 3, g = i & 7;
            *(uint4*)(Bs + sw_off(row, g)) = gb[j];
        }
        __syncthreads();

        if (kc + 1 < D_ / KC_) {
            int co = (kc + 1) * KC_;
#pragma unroll
            for (int j = 0; j < 2; j++) {
                int i = t + j * 128, row = i >> 3, g = i & 7;
                ga[j] = *(const uint4*)(A + (size_t)(brow + row) * D_ + co + g * 8);
            }
#pragma unroll
            for (int j = 0; j < 4; j++) {
                int i = t + j * 128, row = i >> 3, g = i & 7;
                gb[j] = *(const uint4*)(B + (size_t)(bcol + row) * D_ + co + g * 8);
            }
        }

#pragma unroll
        for (int kh = 0; kh < 4; kh++) {
            unsigned af[4], bfr[2][4];
            {
                unsigned ad = asb + sw_off(wr * 16 + rsel, kh * 2 + gsel);
                asm volatile("ldmatrix.sync.aligned.m8n8.x4.shared.b16 {%0,%1,%2,%3}, [%4];"
                             : "=r"(af[0]), "=r"(af[1]), "=r"(af[2]), "=r"(af[3])
                             : "r"(ad));
            }
#pragma unroll
            for (int np = 0; np < 2; np++) {
                unsigned bd = bsb + sw_off(wc * 32 + np * 16 + rsel, kh * 2 + gsel);
                asm volatile("ldmatrix.sync.aligned.m8n8.x4.shared.b16 {%0,%1,%2,%3}, [%4];"
                             : "=r"(bfr[np][0]), "=r"(bfr[np][1]), "=r"(bfr[np][2]), "=r"(bfr[np][3])
                             : "r"(bd));
            }
#pragma unroll
            for (int nt = 0; nt < 4; nt++) {
                int np = nt >> 1, s = nt & 1;
                asm volatile(
                    "mma.sync.aligned.m16n8k16.row.col.f32.bf16.bf16.f32 "
                    "{%0,%1,%2,%3},{%4,%5,%6,%7},{%8,%9},{%0,%1,%2,%3};"
                    : "+f"(acc[nt][0]), "+f"(acc[nt][1]), "+f"(acc[nt][2]), "+f"(acc[nt][3])
                    : "r"(af[0]), "r"(af[1]), "r"(af[2]), "r"(af[3]),
                      "r"(bfr[np][0 + s]), "r"(bfr[np][2 + s]));
            }
        }
        __syncthreads();
    }

    // ---- fused epilogue: per-row sum of exp(2*dot) + diagonal dots ----
    {
        float s0 = 0.f, s1 = 0.f;
#pragma unroll
        for (int nt = 0; nt < 4; nt++) {
            s0 += __expf(2.f * acc[nt][0]) + __expf(2.f * acc[nt][1]);
            s1 += __expf(2.f * acc[nt][2]) + __expf(2.f * acc[nt][3]);
        }
        s0 += __shfl_xor_sync(0xffffffffu, s0, 1);
        s0 += __shfl_xor_sync(0xffffffffu, s0, 2);
        s1 += __shfl_xor_sync(0xffffffffu, s1, 1);
        s1 += __shfl_xor_sync(0xffffffffu, s1, 2);
        if ((lane & 3) == 0) {
            int r0 = brow + wr * 16 + (lane >> 2);
            atomicAdd(&g_expsum[p][r0],     s0);
            atomicAdd(&g_expsum[p][r0 + 8], s1);
        }
    }
    if (brow < bcol + 64 && bcol < brow + 32) {   // diagonal crosses this tile
        float dsum = 0.f;
#pragma unroll
        for (int nt = 0; nt < 4; nt++) {
            int gr = brow + wr * 16 + (lane >> 2);
            int gc = bcol + wc * 32 + nt * 8 + (lane & 3) * 2;
            if (gr == gc)         dsum += acc[nt][0];
            if (gc + 1 == gr)     dsum += acc[nt][1];
            if (gr + 8 == gc)     dsum += acc[nt][2];
            if (gc + 1 == gr + 8) dsum += acc[nt][3];
        }
        if (dsum != 0.f) atomicAdd(&g_sumdiag, dsum);
    }
}

// ---------------- kernel 3: final scalar (1 block, 512) --------------------
__global__ void __launch_bounds__(512) k3_final(float* __restrict__ out) {
    int t = threadIdx.x;
    float L = __logf(g_expsum[0][t]) + __logf(g_expsum[1][t]) + __logf(g_expsum[2][t]);
    __shared__ float w1[16];
    L = warpSum(L);
    if ((t & 31) == 0) w1[t >> 5] = L;
    __syncthreads();
    if (t == 0) {
        float S = 0.f;
        for (int i = 0; i < 16; i++) S += w1[i];
        // loss_intra = 6 - (2/N)*sum||s||
        // loss_inter = (sum log S_r - 2*sum diag) / P
        out[0] = 6.f - g_sumnorm / 4096.f + (S - 2.f * g_sumdiag) / 512.f;
    }
}

// ---------------- launch ----------------------------------------------------
extern "C" void kernel_launch(void* const* d_in, const int* in_sizes, int n_in,
                              void* d_out, int out_size) {
    const float* fv    = (const float*)d_in[0];
    const float* fa    = (const float*)d_in[1];
    const float* fr    = (const float*)d_in[2];
    const int*   label = (const int*)d_in[3];
    (void)in_sizes; (void)n_in; (void)out_size;

    cudaFuncSetAttribute(k1_centers, cudaFuncAttributeMaxDynamicSharedMemorySize,
                         S_ * D_ * (int)sizeof(float));

    k0a_hist<<<NB_, 512>>>(label);
    k0b_fill<<<NB_, 512>>>(label);
    k1_centers<<<dim3(P_, 3), 256, S_ * D_ * sizeof(float)>>>(fv, fa, fr);
    k2_gemm<<<dim3(8, 16, 3), 128>>>();
    k3_final<<<1, 512>>>((float*)d_out);
}